// round 1
// baseline (speedup 1.0000x reference)
#include <cuda_runtime.h>
#include <cuda_bf16.h>

// DynamicUpsamplingFilter: out[b,c,h,w] = sum_{dy,dx} x[b,c,h+dy-1,w+dx-1] * filters[b,dy*3+dx,h,w]
// Shapes: x [4,128,180,320] f32, filters [4,9,180,320] f32, out [4,128,180,320] f32.
//
// Strategy: each thread owns 4 consecutive w-pixels at one (b,h). It loads the
// 9 filter values per pixel ONCE into registers (36 regs, boundary-masked),
// then loops over a 32-channel chunk doing: 3x (float4 + 2 scalar) x-loads,
// 36 FMAs, 1 float4 store. Filters are register-resident across channels.

#define B_ 4
#define C_ 128
#define H_ 180
#define W_ 320
#define CPB 32           // channels per block
#define TPB 256

__global__ __launch_bounds__(TPB)
void duf_kernel(const float* __restrict__ x,
                const float* __restrict__ filters,
                float* __restrict__ out)
{
    const int HW = H_ * W_;
    // spatial thread id: covers B * H * (W/4) = 4*180*80 = 57600 threads
    int tid = blockIdx.x * TPB + threadIdx.x;
    const int WQ = W_ / 4;             // 80
    int wq = tid % WQ;
    int t2 = tid / WQ;
    int h  = t2 % H_;
    int b  = t2 / H_;
    int w  = wq * 4;

    int c0 = blockIdx.y * CPB;

    // ---- load 9 filter float4s (one per tap) for the 4 pixels ----
    const float* fb = filters + ((size_t)b * 9) * HW + (size_t)h * W_ + w;
    float4 f[9];
#pragma unroll
    for (int i = 0; i < 9; i++)
        f[i] = __ldg((const float4*)(fb + (size_t)i * HW));

    // ---- boundary masking folded into filter coefficients ----
    if (h == 0) {                 // taps dy=0 fall off the top
        f[0] = make_float4(0,0,0,0);
        f[1] = make_float4(0,0,0,0);
        f[2] = make_float4(0,0,0,0);
    }
    if (h == H_ - 1) {            // taps dy=2 fall off the bottom
        f[6] = make_float4(0,0,0,0);
        f[7] = make_float4(0,0,0,0);
        f[8] = make_float4(0,0,0,0);
    }
    if (w == 0) {                 // pixel 0's dx=0 taps fall off the left
        f[0].x = 0.f; f[3].x = 0.f; f[6].x = 0.f;
    }
    if (w + 4 == W_) {            // pixel 3's dx=2 taps fall off the right
        f[2].w = 0.f; f[5].w = 0.f; f[8].w = 0.f;
    }

    // clamped row/col addresses (safe reads; masked coeffs make them no-ops)
    int hm = (h > 0)      ? h - 1 : 0;
    int hp = (h < H_ - 1) ? h + 1 : h;
    int wl = (w > 0)      ? w - 1 : 0;
    int wr = (w + 4 < W_) ? w + 4 : W_ - 1;

    const float* base = x + ((size_t)(b * C_ + c0)) * HW;
    const float* pm = base + (size_t)hm * W_;
    const float* p0 = base + (size_t)h  * W_;
    const float* pp = base + (size_t)hp * W_;
    float* po = out + (((size_t)(b * C_ + c0)) * H_ + h) * (size_t)W_ + w;

#pragma unroll 2
    for (int c = 0; c < CPB; c++) {
        float4 vm = __ldg((const float4*)(pm + w));
        float  vml = __ldg(pm + wl);
        float  vmr = __ldg(pm + wr);
        float4 v0 = __ldg((const float4*)(p0 + w));
        float  v0l = __ldg(p0 + wl);
        float  v0r = __ldg(p0 + wr);
        float4 vp = __ldg((const float4*)(pp + w));
        float  vpl = __ldg(pp + wl);
        float  vpr = __ldg(pp + wr);

        float4 acc;
        // pixel 0: taps (vl, v.x, v.y) per row
        acc.x = f[0].x*vml + f[1].x*vm.x + f[2].x*vm.y
              + f[3].x*v0l + f[4].x*v0.x + f[5].x*v0.y
              + f[6].x*vpl + f[7].x*vp.x + f[8].x*vp.y;
        // pixel 1: (v.x, v.y, v.z)
        acc.y = f[0].y*vm.x + f[1].y*vm.y + f[2].y*vm.z
              + f[3].y*v0.x + f[4].y*v0.y + f[5].y*v0.z
              + f[6].y*vp.x + f[7].y*vp.y + f[8].y*vp.z;
        // pixel 2: (v.y, v.z, v.w)
        acc.z = f[0].z*vm.y + f[1].z*vm.z + f[2].z*vm.w
              + f[3].z*v0.y + f[4].z*v0.z + f[5].z*v0.w
              + f[6].z*vp.y + f[7].z*vp.z + f[8].z*vp.w;
        // pixel 3: (v.z, v.w, vr)
        acc.w = f[0].w*vm.z + f[1].w*vm.w + f[2].w*vmr
              + f[3].w*v0.z + f[4].w*v0.w + f[5].w*v0r
              + f[6].w*vp.z + f[7].w*vp.w + f[8].w*vpr;

        *((float4*)po) = acc;

        pm += HW; p0 += HW; pp += HW; po += HW;
    }
}

extern "C" void kernel_launch(void* const* d_in, const int* in_sizes, int n_in,
                              void* d_out, int out_size)
{
    const float* x       = (const float*)d_in[0];
    const float* filters = (const float*)d_in[1];
    float* out           = (float*)d_out;

    int spatial_threads = B_ * H_ * (W_ / 4);     // 57600
    dim3 grid(spatial_threads / TPB, C_ / CPB);   // (225, 4)
    duf_kernel<<<grid, TPB>>>(x, filters, out);
}

// round 2
// speedup vs baseline: 1.0270x; 1.0270x over previous
#include <cuda_runtime.h>
#include <cuda_bf16.h>

// DynamicUpsamplingFilter: out[b,c,h,w] = sum_{dy,dx} x[b,c,h+dy-1,w+dx-1] * filters[b,dy*3+dx,h,w]
// x [4,128,180,320] f32, filters [4,9,180,320] f32, out [4,128,180,320] f32.
//
// R2: halo values come from neighbor lanes via __shfl (they already hold them
// in registers) instead of strided scalar LDGs. Only warp-edge lanes (0, 31)
// do a predicated 1-lane load. Row-crossing shuffle garbage is neutralized by
// the zero-masked boundary coefficients. Cuts L1 wavefronts per channel-iter
// from ~40 to ~17; unroll 4 for load MLP.

#define B_ 4
#define C_ 128
#define H_ 180
#define W_ 320
#define CPB 32           // channels per block (grid.y = 4)
#define TPB 256

__global__ __launch_bounds__(TPB)
void duf_kernel(const float* __restrict__ x,
                const float* __restrict__ filters,
                float* __restrict__ out)
{
    const int HW = H_ * W_;
    int tid = blockIdx.x * TPB + threadIdx.x;
    const int WQ = W_ / 4;             // 80
    int wq = tid % WQ;
    int t2 = tid / WQ;
    int h  = t2 % H_;
    int b  = t2 / H_;
    int w  = wq * 4;
    int lane = threadIdx.x & 31;

    int c0 = blockIdx.y * CPB;

    // ---- 9 filter float4s (one per tap) for this thread's 4 pixels ----
    const float* fb = filters + ((size_t)b * 9) * HW + (size_t)h * W_ + w;
    float4 f[9];
#pragma unroll
    for (int i = 0; i < 9; i++)
        f[i] = __ldg((const float4*)(fb + (size_t)i * HW));

    // ---- boundary masking folded into coefficients ----
    if (h == 0) {
        f[0] = make_float4(0,0,0,0);
        f[1] = make_float4(0,0,0,0);
        f[2] = make_float4(0,0,0,0);
    }
    if (h == H_ - 1) {
        f[6] = make_float4(0,0,0,0);
        f[7] = make_float4(0,0,0,0);
        f[8] = make_float4(0,0,0,0);
    }
    if (w == 0) {                 // pixel 0's dx=0 taps off the left
        f[0].x = 0.f; f[3].x = 0.f; f[6].x = 0.f;
    }
    if (w + 4 == W_) {            // pixel 3's dx=2 taps off the right
        f[2].w = 0.f; f[5].w = 0.f; f[8].w = 0.f;
    }

    // clamped addresses (reads are safe; masked coeffs make values no-ops)
    int hm = (h > 0)      ? h - 1 : 0;
    int hp = (h < H_ - 1) ? h + 1 : h;
    int wl = (w > 0)      ? w - 1 : 0;
    int wr = (w + 4 < W_) ? w + 4 : W_ - 1;

    const bool ld_l = (lane == 0);    // left halo not available via shuffle
    const bool ld_r = (lane == 31);   // right halo not available via shuffle

    const float* base = x + ((size_t)(b * C_ + c0)) * HW;
    const float* pm = base + (size_t)hm * W_;
    const float* p0 = base + (size_t)h  * W_;
    const float* pp = base + (size_t)hp * W_;
    float* po = out + (((size_t)(b * C_ + c0)) * H_ + h) * (size_t)W_ + w;

#pragma unroll 4
    for (int c = 0; c < CPB; c++) {
        float4 vm = __ldg((const float4*)(pm + w));
        float4 v0 = __ldg((const float4*)(p0 + w));
        float4 vp = __ldg((const float4*)(pp + w));

        // halos from neighbor lanes (already register-resident there)
        float vml = __shfl_up_sync(0xffffffffu,  vm.w, 1);
        float v0l = __shfl_up_sync(0xffffffffu,  v0.w, 1);
        float vpl = __shfl_up_sync(0xffffffffu,  vp.w, 1);
        float vmr = __shfl_down_sync(0xffffffffu, vm.x, 1);
        float v0r = __shfl_down_sync(0xffffffffu, v0.x, 1);
        float vpr = __shfl_down_sync(0xffffffffu, vp.x, 1);

        // warp-edge lanes: 1-lane predicated loads (L1 hits, 1 sector)
        if (ld_l) {
            vml = __ldg(pm + wl);
            v0l = __ldg(p0 + wl);
            vpl = __ldg(pp + wl);
        }
        if (ld_r) {
            vmr = __ldg(pm + wr);
            v0r = __ldg(p0 + wr);
            vpr = __ldg(pp + wr);
        }

        float4 acc;
        acc.x = f[0].x*vml  + f[1].x*vm.x + f[2].x*vm.y
              + f[3].x*v0l  + f[4].x*v0.x + f[5].x*v0.y
              + f[6].x*vpl  + f[7].x*vp.x + f[8].x*vp.y;
        acc.y = f[0].y*vm.x + f[1].y*vm.y + f[2].y*vm.z
              + f[3].y*v0.x + f[4].y*v0.y + f[5].y*v0.z
              + f[6].y*vp.x + f[7].y*vp.y + f[8].y*vp.z;
        acc.z = f[0].z*vm.y + f[1].z*vm.z + f[2].z*vm.w
              + f[3].z*v0.y + f[4].z*v0.z + f[5].z*v0.w
              + f[6].z*vp.y + f[7].z*vp.z + f[8].z*vp.w;
        acc.w = f[0].w*vm.z + f[1].w*vm.w + f[2].w*vmr
              + f[3].w*v0.z + f[4].w*v0.w + f[5].w*v0r
              + f[6].w*vp.z + f[7].w*vp.w + f[8].w*vpr;

        *((float4*)po) = acc;

        pm += HW; p0 += HW; pp += HW; po += HW;
    }
}

extern "C" void kernel_launch(void* const* d_in, const int* in_sizes, int n_in,
                              void* d_out, int out_size)
{
    const float* x       = (const float*)d_in[0];
    const float* filters = (const float*)d_in[1];
    float* out           = (float*)d_out;

    int spatial_threads = B_ * H_ * (W_ / 4);     // 57600
    dim3 grid(spatial_threads / TPB, C_ / CPB);   // (225, 4)
    duf_kernel<<<grid, TPB>>>(x, filters, out);
}

// round 3
// speedup vs baseline: 1.0519x; 1.0242x over previous
#include <cuda_runtime.h>
#include <cuda_bf16.h>

// DynamicUpsamplingFilter: out[b,c,h,w] = sum_{dy,dx} x[b,c,h+dy-1,w+dx-1] * filters[b,dy*3+dx,h,w]
// x [4,128,180,320] f32, filters [4,9,180,320] f32, out [4,128,180,320] f32.
//
// R3: occupancy-first rebuild. 2 pixels/thread (float2) so the register-resident
// filter set is 18 regs instead of 36; __launch_bounds__(256,4) -> <=64 regs,
// 4 CTAs/SM, 32 warps (50% occ) vs previous 16 (24%). Halos via lane shuffles,
// warp-edge lanes use predicated 1-lane loads. Rows are 160 threads (=5 warps),
// so rows never cross mid-warp: row starts land on lane 0, row ends on lane 31,
// exactly the lanes already doing predicated loads.

#define B_ 4
#define C_ 128
#define H_ 180
#define W_ 320
#define CPB 16           // channels per block (grid.y = 8)
#define TPB 256

__global__ __launch_bounds__(TPB, 4)
void duf_kernel(const float* __restrict__ x,
                const float* __restrict__ filters,
                float* __restrict__ out)
{
    const int HW = H_ * W_;
    int tid = blockIdx.x * TPB + threadIdx.x;
    const int WH = W_ / 2;             // 160 thread-pairs per row
    int wh = tid % WH;
    int t2 = tid / WH;
    int h  = t2 % H_;
    int b  = t2 / H_;
    int w  = wh * 2;
    int lane = threadIdx.x & 31;

    int c0 = blockIdx.y * CPB;

    // ---- 9 filter float2s (one per tap) for this thread's 2 pixels ----
    const float* fb = filters + ((size_t)b * 9) * HW + (size_t)h * W_ + w;
    float2 f[9];
#pragma unroll
    for (int i = 0; i < 9; i++)
        f[i] = __ldg((const float2*)(fb + (size_t)i * HW));

    // ---- boundary masking folded into coefficients ----
    if (h == 0) {
        f[0] = make_float2(0.f, 0.f);
        f[1] = make_float2(0.f, 0.f);
        f[2] = make_float2(0.f, 0.f);
    }
    if (h == H_ - 1) {
        f[6] = make_float2(0.f, 0.f);
        f[7] = make_float2(0.f, 0.f);
        f[8] = make_float2(0.f, 0.f);
    }
    if (w == 0) {                 // pixel 0's dx=0 taps off the left
        f[0].x = 0.f; f[3].x = 0.f; f[6].x = 0.f;
    }
    if (w + 2 == W_) {            // pixel 1's dx=2 taps off the right
        f[2].y = 0.f; f[5].y = 0.f; f[8].y = 0.f;
    }

    // clamped addresses (reads safe; masked coeffs neutralize values)
    int hm = (h > 0)      ? h - 1 : 0;
    int hp = (h < H_ - 1) ? h + 1 : h;
    int wl = (w > 0)      ? w - 1 : 0;
    int wr = (w + 2 < W_) ? w + 2 : W_ - 1;

    const bool ld_l = (lane == 0);
    const bool ld_r = (lane == 31);

    const float* base = x + ((size_t)(b * C_ + c0)) * HW;
    const float* pm = base + (size_t)hm * W_;
    const float* p0 = base + (size_t)h  * W_;
    const float* pp = base + (size_t)hp * W_;
    float* po = out + (((size_t)(b * C_ + c0)) * H_ + h) * (size_t)W_ + w;

#pragma unroll 2
    for (int c = 0; c < CPB; c++) {
        float2 vm = __ldg((const float2*)(pm + w));
        float2 v0 = __ldg((const float2*)(p0 + w));
        float2 vp = __ldg((const float2*)(pp + w));

        // halos from neighbor lanes
        float vml = __shfl_up_sync(0xffffffffu,  vm.y, 1);
        float v0l = __shfl_up_sync(0xffffffffu,  v0.y, 1);
        float vpl = __shfl_up_sync(0xffffffffu,  vp.y, 1);
        float vmr = __shfl_down_sync(0xffffffffu, vm.x, 1);
        float v0r = __shfl_down_sync(0xffffffffu, v0.x, 1);
        float vpr = __shfl_down_sync(0xffffffffu, vp.x, 1);

        if (ld_l) {
            vml = __ldg(pm + wl);
            v0l = __ldg(p0 + wl);
            vpl = __ldg(pp + wl);
        }
        if (ld_r) {
            vmr = __ldg(pm + wr);
            v0r = __ldg(p0 + wr);
            vpr = __ldg(pp + wr);
        }

        float2 acc;
        acc.x = f[0].x*vml  + f[1].x*vm.x + f[2].x*vm.y
              + f[3].x*v0l  + f[4].x*v0.x + f[5].x*v0.y
              + f[6].x*vpl  + f[7].x*vp.x + f[8].x*vp.y;
        acc.y = f[0].y*vm.x + f[1].y*vm.y + f[2].y*vmr
              + f[3].y*v0.x + f[4].y*v0.y + f[5].y*v0r
              + f[6].y*vp.x + f[7].y*vp.y + f[8].y*vpr;

        *((float2*)po) = acc;

        pm += HW; p0 += HW; pp += HW; po += HW;
    }
}

extern "C" void kernel_launch(void* const* d_in, const int* in_sizes, int n_in,
                              void* d_out, int out_size)
{
    const float* x       = (const float*)d_in[0];
    const float* filters = (const float*)d_in[1];
    float* out           = (float*)d_out;

    int spatial_threads = B_ * H_ * (W_ / 2);     // 115200
    dim3 grid(spatial_threads / TPB, C_ / CPB);   // (450, 8) = 3600 blocks
    duf_kernel<<<grid, TPB>>>(x, filters, out);
}

// round 4
// speedup vs baseline: 1.3646x; 1.2973x over previous
#include <cuda_runtime.h>
#include <cuda_bf16.h>

// DynamicUpsamplingFilter: out[b,c,h,w] = sum_{dy,dx} x[b,c,h+dy-1,w+dx-1] * filters[b,dy*3+dx,h,w]
// x [4,128,180,320] f32, filters [4,9,180,320] f32, out [4,128,180,320] f32.
//
// R4: MLP-first. All halo values come from extra CONTIGUOUS coalesced loads
// (float2 at w-2 -> .y is x(w-1); scalar at w+2) instead of shuffles or
// strided scalars. Every load in the channel loop is independent -> ptxas
// front-batches 18 LDGs per unroll-2 block (~16 distinct 128B lines in
// flight per warp per stall). Boundary handling is fully hoisted: zeroed
// filter coefficients + clamped per-thread offsets; hot loop has no
// branches, no predicated loads, no shuffles.

#define B_ 4
#define C_ 128
#define H_ 180
#define W_ 320
#define CPB 32           // channels per block (grid.y = 4)
#define TPB 256

__global__ __launch_bounds__(TPB, 3)
void duf_kernel(const float* __restrict__ x,
                const float* __restrict__ filters,
                float* __restrict__ out)
{
    const int HW = H_ * W_;
    int tid = blockIdx.x * TPB + threadIdx.x;
    const int WH = W_ / 2;             // 160 pixel-pairs per row
    int wh = tid % WH;
    int t2 = tid / WH;
    int h  = t2 % H_;
    int b  = t2 / H_;
    int w  = wh * 2;

    int c0 = blockIdx.y * CPB;

    // ---- 9 filter float2s (tap i, pixels w and w+1) ----
    const float* fb = filters + ((size_t)b * 9) * HW + (size_t)h * W_ + w;
    float2 f[9];
#pragma unroll
    for (int i = 0; i < 9; i++)
        f[i] = __ldg((const float2*)(fb + (size_t)i * HW));

    // ---- boundary masking folded into coefficients ----
    if (h == 0) {
        f[0] = make_float2(0.f, 0.f);
        f[1] = make_float2(0.f, 0.f);
        f[2] = make_float2(0.f, 0.f);
    }
    if (h == H_ - 1) {
        f[6] = make_float2(0.f, 0.f);
        f[7] = make_float2(0.f, 0.f);
        f[8] = make_float2(0.f, 0.f);
    }
    if (w == 0) {                  // pixel0 left taps off the edge
        f[0].x = 0.f; f[3].x = 0.f; f[6].x = 0.f;
    }
    if (w + 2 == W_) {             // pixel1 right taps off the edge
        f[2].y = 0.f; f[5].y = 0.f; f[8].y = 0.f;
    }

    // clamped per-thread offsets (values at clamps are multiplied by 0)
    int hm  = (h > 0)      ? h - 1 : 0;
    int hp  = (h < H_ - 1) ? h + 1 : h;
    int wl2 = (w >= 2)     ? w - 2 : 0;        // float2 covering [w-2, w-1]
    int ws  = (w + 2 < W_) ? w + 2 : W_ - 1;   // scalar x(w+2)

    const float* base = x + ((size_t)(b * C_ + c0)) * HW;
    const float* pm = base + (size_t)hm * W_;
    const float* p0 = base + (size_t)h  * W_;
    const float* pp = base + (size_t)hp * W_;
    float* po = out + (((size_t)(b * C_ + c0)) * H_ + h) * (size_t)W_ + w;

#pragma unroll 2
    for (int c = 0; c < CPB; c++) {
        // 9 independent loads: main pair + left pair + right scalar per row
        float2 vm = __ldg((const float2*)(pm + w));
        float2 lm = __ldg((const float2*)(pm + wl2));
        float  sm = __ldg(pm + ws);
        float2 v0 = __ldg((const float2*)(p0 + w));
        float2 l0 = __ldg((const float2*)(p0 + wl2));
        float  s0 = __ldg(p0 + ws);
        float2 vp = __ldg((const float2*)(pp + w));
        float2 lp = __ldg((const float2*)(pp + wl2));
        float  sp = __ldg(pp + ws);

        float2 acc;
        acc.x = f[0].x*lm.y + f[1].x*vm.x + f[2].x*vm.y
              + f[3].x*l0.y + f[4].x*v0.x + f[5].x*v0.y
              + f[6].x*lp.y + f[7].x*vp.x + f[8].x*vp.y;
        acc.y = f[0].y*vm.x + f[1].y*vm.y + f[2].y*sm
              + f[3].y*v0.x + f[4].y*v0.y + f[5].y*s0
              + f[6].y*vp.x + f[7].y*vp.y + f[8].y*sp;

        *((float2*)po) = acc;

        pm += HW; p0 += HW; pp += HW; po += HW;
    }
}

extern "C" void kernel_launch(void* const* d_in, const int* in_sizes, int n_in,
                              void* d_out, int out_size)
{
    const float* x       = (const float*)d_in[0];
    const float* filters = (const float*)d_in[1];
    float* out           = (float*)d_out;

    int spatial_threads = B_ * H_ * (W_ / 2);     // 115200
    dim3 grid(spatial_threads / TPB, C_ / CPB);   // (450, 4) = 1800 blocks
    duf_kernel<<<grid, TPB>>>(x, filters, out);
}

// round 5
// speedup vs baseline: 1.5860x; 1.1622x over previous
#include <cuda_runtime.h>
#include <cuda_bf16.h>

// DynamicUpsamplingFilter: out[b,c,h,w] = sum_{dy,dx} x[b,c,h+dy-1,w+dx-1] * filters[b,dy*3+dx,h,w]
// x [4,128,180,320] f32, filters [4,9,180,320] f32, out [4,128,180,320] f32.
//
// R5: R4 (independent contiguous loads, hoisted boundary masks) + explicit
// two-phase unroll-4 staging: load ALL 36 values for 4 channel-iterations
// into register arrays first (independent -> ptxas front-batches ~28 distinct
// 128B lines per warp per stall region), then compute+store. Doubles per-warp
// MLP_eff vs R4's unroll-2.

#define B_ 4
#define C_ 128
#define H_ 180
#define W_ 320
#define CPB 32           // channels per block (grid.y = 4)
#define TPB 256
#define U   4            // channel unroll (staged)

__global__ __launch_bounds__(TPB, 3)
void duf_kernel(const float* __restrict__ x,
                const float* __restrict__ filters,
                float* __restrict__ out)
{
    const int HW = H_ * W_;
    int tid = blockIdx.x * TPB + threadIdx.x;
    const int WH = W_ / 2;             // 160 pixel-pairs per row
    int wh = tid % WH;
    int t2 = tid / WH;
    int h  = t2 % H_;
    int b  = t2 / H_;
    int w  = wh * 2;

    int c0 = blockIdx.y * CPB;

    // ---- 9 filter float2s (tap i, pixels w and w+1) ----
    const float* fb = filters + ((size_t)b * 9) * HW + (size_t)h * W_ + w;
    float2 f[9];
#pragma unroll
    for (int i = 0; i < 9; i++)
        f[i] = __ldg((const float2*)(fb + (size_t)i * HW));

    // ---- boundary masking folded into coefficients ----
    if (h == 0) {
        f[0] = make_float2(0.f, 0.f);
        f[1] = make_float2(0.f, 0.f);
        f[2] = make_float2(0.f, 0.f);
    }
    if (h == H_ - 1) {
        f[6] = make_float2(0.f, 0.f);
        f[7] = make_float2(0.f, 0.f);
        f[8] = make_float2(0.f, 0.f);
    }
    if (w == 0) {                  // pixel0 left taps off the edge
        f[0].x = 0.f; f[3].x = 0.f; f[6].x = 0.f;
    }
    if (w + 2 == W_) {             // pixel1 right taps off the edge
        f[2].y = 0.f; f[5].y = 0.f; f[8].y = 0.f;
    }

    // clamped per-thread offsets (values at clamps are multiplied by 0)
    int hm  = (h > 0)      ? h - 1 : 0;
    int hp  = (h < H_ - 1) ? h + 1 : h;
    int wl2 = (w >= 2)     ? w - 2 : 0;        // float2 covering [w-2, w-1]
    int ws  = (w + 2 < W_) ? w + 2 : W_ - 1;   // scalar x(w+2)

    const float* base = x + ((size_t)(b * C_ + c0)) * HW;
    const float* pm = base + (size_t)hm * W_;
    const float* p0 = base + (size_t)h  * W_;
    const float* pp = base + (size_t)hp * W_;
    float* po = out + (((size_t)(b * C_ + c0)) * H_ + h) * (size_t)W_ + w;

    for (int c = 0; c < CPB; c += U) {
        float2 vm[U], lm[U], v0[U], l0[U], vp[U], lp[U];
        float  sm[U], s0[U], sp[U];

        // ---- phase 1: 9*U independent loads, front-batched ----
#pragma unroll
        for (int u = 0; u < U; u++) {
            const float* qm = pm + (size_t)u * HW;
            const float* q0 = p0 + (size_t)u * HW;
            const float* qp = pp + (size_t)u * HW;
            vm[u] = __ldg((const float2*)(qm + w));
            lm[u] = __ldg((const float2*)(qm + wl2));
            sm[u] = __ldg(qm + ws);
            v0[u] = __ldg((const float2*)(q0 + w));
            l0[u] = __ldg((const float2*)(q0 + wl2));
            s0[u] = __ldg(q0 + ws);
            vp[u] = __ldg((const float2*)(qp + w));
            lp[u] = __ldg((const float2*)(qp + wl2));
            sp[u] = __ldg(qp + ws);
        }

        // ---- phase 2: compute + store ----
#pragma unroll
        for (int u = 0; u < U; u++) {
            float2 acc;
            acc.x = f[0].x*lm[u].y + f[1].x*vm[u].x + f[2].x*vm[u].y
                  + f[3].x*l0[u].y + f[4].x*v0[u].x + f[5].x*v0[u].y
                  + f[6].x*lp[u].y + f[7].x*vp[u].x + f[8].x*vp[u].y;
            acc.y = f[0].y*vm[u].x + f[1].y*vm[u].y + f[2].y*sm[u]
                  + f[3].y*v0[u].x + f[4].y*v0[u].y + f[5].y*s0[u]
                  + f[6].y*vp[u].x + f[7].y*vp[u].y + f[8].y*sp[u];
            *((float2*)(po + (size_t)u * HW)) = acc;
        }

        pm += (size_t)U * HW;
        p0 += (size_t)U * HW;
        pp += (size_t)U * HW;
        po += (size_t)U * HW;
    }
}

extern "C" void kernel_launch(void* const* d_in, const int* in_sizes, int n_in,
                              void* d_out, int out_size)
{
    const float* x       = (const float*)d_in[0];
    const float* filters = (const float*)d_in[1];
    float* out           = (float*)d_out;

    int spatial_threads = B_ * H_ * (W_ / 2);     // 115200
    dim3 grid(spatial_threads / TPB, C_ / CPB);   // (450, 4) = 1800 blocks
    duf_kernel<<<grid, TPB>>>(x, filters, out);
}